// round 1
// baseline (speedup 1.0000x reference)
#include <cuda_runtime.h>
#include <cuda_bf16.h>
#include <math.h>

// Problem constants
#define B_   16
#define Q_   300
#define S_   8400
#define DM   256
#define NH   8
#define HD   32
#define LP_  12
#define BQ   (B_*Q_)          // 4800
#define MVAL (B_*S_)          // 134400

// Scratch (static device globals — no allocation)
__device__ float g_value[(size_t)MVAL * DM];   // [B,S,H,HD] = [B,S,256]
__device__ float g_offs[(size_t)BQ * 192];     // raw offsets [B*Q, H*LP*2]
__device__ float g_attn[(size_t)BQ * 96];      // attn logits [B*Q, H*LP]
__device__ float g_msda[(size_t)BQ * DM];      // sampled output [B*Q, 256]

// ---------------------------------------------------------------------------
// Generic fp32 GEMM: C[M,N] = A[M,K] * W[N,K]^T + bias[N]
// BM=128, BN=64, BK=16, 256 threads, 8x4 microtile per thread.
// ---------------------------------------------------------------------------
#define BM 128
#define BN 64
#define BK 16
#define TM 8
#define TN 4

__global__ __launch_bounds__(256) void gemm_nt_bias(
    const float* __restrict__ A, const float* __restrict__ W,
    const float* __restrict__ bias, float* __restrict__ C,
    int M, int N, int K)
{
    __shared__ float As[BK][BM + 4];
    __shared__ float Bs[BK][BN];

    const int tx = threadIdx.x & 15;   // n direction (16)
    const int ty = threadIdx.x >> 4;   // m direction (16)
    const int bm = blockIdx.y * BM;
    const int bn = blockIdx.x * BN;

    float acc[TM][TN];
#pragma unroll
    for (int i = 0; i < TM; i++)
#pragma unroll
        for (int j = 0; j < TN; j++) acc[i][j] = 0.f;

    for (int k0 = 0; k0 < K; k0 += BK) {
        // A tile: BM x BK = 2048 elems / 256 threads = 8 each
#pragma unroll
        for (int t = 0; t < (BM * BK) / 256; ++t) {
            int i = threadIdx.x + t * 256;
            int m = i / BK, k = i % BK;
            float v = 0.f;
            if (bm + m < M) v = A[(size_t)(bm + m) * K + k0 + k];
            As[k][m] = v;
        }
        // W tile: BN x BK = 1024 elems / 256 threads = 4 each
#pragma unroll
        for (int t = 0; t < (BN * BK) / 256; ++t) {
            int i = threadIdx.x + t * 256;
            int n = i / BK, k = i % BK;
            float v = 0.f;
            if (bn + n < N) v = W[(size_t)(bn + n) * K + k0 + k];
            Bs[k][n] = v;
        }
        __syncthreads();

#pragma unroll
        for (int k = 0; k < BK; ++k) {
            float a[TM], b[TN];
#pragma unroll
            for (int i = 0; i < TM; i++) a[i] = As[k][ty * TM + i];
#pragma unroll
            for (int j = 0; j < TN; j++) b[j] = Bs[k][tx * TN + j];
#pragma unroll
            for (int i = 0; i < TM; i++)
#pragma unroll
                for (int j = 0; j < TN; j++) acc[i][j] += a[i] * b[j];
        }
        __syncthreads();
    }

#pragma unroll
    for (int i = 0; i < TM; i++) {
        int m = bm + ty * TM + i;
        if (m >= M) continue;
#pragma unroll
        for (int j = 0; j < TN; j++) {
            int n = bn + tx * TN + j;
            if (n < N) C[(size_t)m * N + n] = acc[i][j] + bias[n];
        }
    }
}

// ---------------------------------------------------------------------------
// Sampling kernel: one warp per (b, q, head); lane = head_dim channel.
// value layout: [B, S, NH, HD] (d contiguous -> coalesced 128B gathers)
// ---------------------------------------------------------------------------
__global__ __launch_bounds__(256) void msda_sample(
    const float* __restrict__ value,   // g_value
    const float* __restrict__ offs,    // g_offs  [BQ,192]
    const float* __restrict__ attnl,   // g_attn  [BQ,96]
    const float* __restrict__ refp,    // [B,Q,1,4]
    float* __restrict__ out)           // g_msda [BQ,256]
{
    const int bq   = blockIdx.x;
    const int b    = bq / Q_;
    const int head = threadIdx.x >> 5;
    const int lane = threadIdx.x & 31;

    const float rx = refp[bq * 4 + 0];
    const float ry = refp[bq * 4 + 1];
    const float rw = refp[bq * 4 + 2];
    const float rh = refp[bq * 4 + 3];

    const float* o  = offs  + (size_t)bq * 192 + head * (LP_ * 2);
    const float* al = attnl + (size_t)bq * 96  + head * LP_;

    // softmax over LP_ (lane-uniform, redundantly computed per lane)
    float w[LP_];
    float mx = -1e30f;
#pragma unroll
    for (int p = 0; p < LP_; p++) { w[p] = al[p]; mx = fmaxf(mx, w[p]); }
    float sum = 0.f;
#pragma unroll
    for (int p = 0; p < LP_; p++) { w[p] = __expf(w[p] - mx); sum += w[p]; }
    const float inv = 1.f / sum;

    float acc = 0.f;
#pragma unroll
    for (int p = 0; p < LP_; p++) {
        const int lvl   = p >> 2;
        const int Wl    = (lvl == 0) ? 80 : (lvl == 1) ? 40 : 20;
        const int Hl    = Wl;
        const int start = (lvl == 0) ? 0 : (lvl == 1) ? 6400 : 8000;

        const float lx = rx + o[2 * p + 0] * 0.125f * rw;  // (1/4)*0.5
        const float ly = ry + o[2 * p + 1] * 0.125f * rh;
        const float gx = lx * (float)Wl - 0.5f;
        const float gy = ly * (float)Hl - 0.5f;

        const float x0f = floorf(gx), y0f = floorf(gy);
        const int x0 = (int)x0f, y0 = (int)y0f;
        const int x1 = x0 + 1,  y1 = y0 + 1;
        const float wx1 = gx - x0f, wx0 = 1.f - wx1;
        const float wy1 = gy - y0f, wy0 = 1.f - wy1;

        const float aw = w[p] * inv;

        const size_t base = ((size_t)b * S_ + start) * DM + head * HD + lane;

        float v00 = 0.f, v10 = 0.f, v01 = 0.f, v11 = 0.f;
        const bool xv0 = (x0 >= 0) & (x0 < Wl);
        const bool xv1 = (x1 >= 0) & (x1 < Wl);
        const bool yv0 = (y0 >= 0) & (y0 < Hl);
        const bool yv1 = (y1 >= 0) & (y1 < Hl);
        if (yv0) {
            const size_t rb = base + (size_t)(y0 * Wl) * DM;
            if (xv0) v00 = value[rb + (size_t)x0 * DM];
            if (xv1) v10 = value[rb + (size_t)x1 * DM];
        }
        if (yv1) {
            const size_t rb = base + (size_t)(y1 * Wl) * DM;
            if (xv0) v01 = value[rb + (size_t)x0 * DM];
            if (xv1) v11 = value[rb + (size_t)x1 * DM];
        }
        acc += aw * (wx0 * wy0 * v00 + wx1 * wy0 * v10 +
                     wx0 * wy1 * v01 + wx1 * wy1 * v11);
    }

    out[(size_t)bq * DM + head * HD + lane] = acc;
}

// ---------------------------------------------------------------------------
extern "C" void kernel_launch(void* const* d_in, const int* in_sizes, int n_in,
                              void* d_out, int out_size)
{
    const float* hs      = (const float*)d_in[0];   // [16,300,256]
    const float* ehs     = (const float*)d_in[1];   // [16,8400,256]
    const float* refp    = (const float*)d_in[2];   // [16,300,1,4]
    const float* w_value = (const float*)d_in[3];   // [256,256]
    const float* b_value = (const float*)d_in[4];   // [256]
    const float* w_off   = (const float*)d_in[5];   // [192,256]
    const float* b_off   = (const float*)d_in[6];   // [192]
    const float* w_attn  = (const float*)d_in[7];   // [96,256]
    const float* b_attn  = (const float*)d_in[8];   // [96]
    const float* w_out   = (const float*)d_in[9];   // [256,256]
    const float* b_out   = (const float*)d_in[10];  // [256]
    float* out = (float*)d_out;

    float *pval, *poff, *pattn, *pmsda;
    cudaGetSymbolAddress((void**)&pval,  g_value);
    cudaGetSymbolAddress((void**)&poff,  g_offs);
    cudaGetSymbolAddress((void**)&pattn, g_attn);
    cudaGetSymbolAddress((void**)&pmsda, g_msda);

    // 1. value = ehs @ w_value^T + b_value   (M=134400, N=256, K=256)
    gemm_nt_bias<<<dim3(DM / BN, MVAL / BM), 256>>>(ehs, w_value, b_value, pval,
                                                    MVAL, DM, DM);
    // 2. offsets = hs @ w_offsets^T + b      (M=4800, N=192, K=256)
    gemm_nt_bias<<<dim3(3, (BQ + BM - 1) / BM), 256>>>(hs, w_off, b_off, poff,
                                                       BQ, 192, DM);
    // 3. attn logits = hs @ w_attn^T + b     (M=4800, N=96, K=256)
    gemm_nt_bias<<<dim3(2, (BQ + BM - 1) / BM), 256>>>(hs, w_attn, b_attn, pattn,
                                                       BQ, 96, DM);
    // 4. softmax + bilinear sampling + weighted sum
    msda_sample<<<BQ, 256>>>(pval, poff, pattn, refp, pmsda);

    // 5. out = msda @ w_out^T + b_out        (M=4800, N=256, K=256)
    gemm_nt_bias<<<dim3(DM / BN, (BQ + BM - 1) / BM), 256>>>(pmsda, w_out, b_out,
                                                             out, BQ, DM, DM);
}

// round 3
// speedup vs baseline: 2.8197x; 2.8197x over previous
#include <cuda_runtime.h>
#include <cuda_bf16.h>
#include <cstdint>
#include <math.h>

// Problem constants
#define B_   16
#define Q_   300
#define S_   8400
#define DM   256
#define NH   8
#define HD   32
#define LP_  12
#define BQ   (B_*Q_)          // 4800
#define MVAL (B_*S_)          // 134400

// Scratch (static device globals — no allocation)
__device__ float g_value[(size_t)MVAL * DM];   // [B,S,256]
__device__ float g_offs[(size_t)BQ * 192];
__device__ float g_attn[(size_t)BQ * 96];
__device__ float g_msda[(size_t)BQ * DM];

// ===========================================================================
// tf32 helpers
// ===========================================================================
__device__ __forceinline__ uint32_t f2tf32(float f) {
    uint32_t u;
    asm("cvt.rna.tf32.f32 %0, %1;" : "=r"(u) : "f"(f));
    return u;
}

__device__ __forceinline__ void mma_m16n8k8_tf32(
    float c[4], const uint32_t a[4], const uint32_t b[2])
{
    asm volatile(
        "mma.sync.aligned.m16n8k8.row.col.f32.tf32.tf32.f32 "
        "{%0,%1,%2,%3}, {%4,%5,%6,%7}, {%8,%9}, {%0,%1,%2,%3};"
        : "+f"(c[0]), "+f"(c[1]), "+f"(c[2]), "+f"(c[3])
        : "r"(a[0]), "r"(a[1]), "r"(a[2]), "r"(a[3]),
          "r"(b[0]), "r"(b[1]));
}

// ===========================================================================
// tf32 tensor-core GEMM: C[M,256] = A[M,256] @ W[256,256]^T + bias
// CTA tile 128x128 (gridDim.x = 2 for N=256), 8 warps (4 m x 2 n),
// warp tile 32x64, BK=32, double-buffered SMEM, fp32->tf32 at SMEM store.
// SMEM: padded [row][36] words -> conflict-free fragment loads.
// ===========================================================================
#define GK    256
#define GBK   32
#define GNC   (GK / GBK)       // 8 chunks
#define PADW  36               // words per row (32 + 4 pad)
#define TILEW (128 * PADW)     // words per (A or B) tile = 4608
#define BUFW  (2 * TILEW)      // words per buffer (A + B)

__global__ __launch_bounds__(256) void gemm_tf32_nt(
    const float* __restrict__ A, const float* __restrict__ W,
    const float* __restrict__ bias, float* __restrict__ C, int M)
{
    extern __shared__ uint32_t sm[];   // 2 buffers x (Atile + Btile)

    const int tid  = threadIdx.x;
    const int wid  = tid >> 5;
    const int lane = tid & 31;
    const int grp  = lane >> 2;        // 0..7
    const int tig  = lane & 3;         // 0..3

    const int wm = (wid & 3) * 32;     // warp m offset in tile
    const int wn = (wid >> 2) * 64;    // warp n offset in tile
    const int bm = blockIdx.y * 128;
    const int bn = blockIdx.x * 128;

    float acc[2][8][4];
#pragma unroll
    for (int i = 0; i < 2; i++)
#pragma unroll
        for (int j = 0; j < 8; j++)
#pragma unroll
            for (int l = 0; l < 4; l++) acc[i][j][l] = 0.f;

    // per-thread global load coords (4 float4 per tile each for A and B)
    const int lrow = tid >> 3;         // 0..31 (row group; +32 per t)
    const int lc4  = tid & 7;          // float4 column 0..7

    // ---- preload chunk 0 ----
    {
        uint32_t* sA = sm;
        uint32_t* sB = sm + TILEW;
#pragma unroll
        for (int t = 0; t < 4; ++t) {
            int row = lrow + t * 32;
            int mg  = bm + row;
            float4 v = make_float4(0.f, 0.f, 0.f, 0.f);
            if (mg < M) v = *(const float4*)(A + (size_t)mg * GK + lc4 * 4);
            uint32_t* d = &sA[row * PADW + lc4 * 4];
            ((uint4*)d)[0] = make_uint4(f2tf32(v.x), f2tf32(v.y), f2tf32(v.z), f2tf32(v.w));
        }
#pragma unroll
        for (int t = 0; t < 4; ++t) {
            int row = lrow + t * 32;
            float4 v = *(const float4*)(W + (size_t)(bn + row) * GK + lc4 * 4);
            uint32_t* d = &sB[row * PADW + lc4 * 4];
            ((uint4*)d)[0] = make_uint4(f2tf32(v.x), f2tf32(v.y), f2tf32(v.z), f2tf32(v.w));
        }
    }
    __syncthreads();

    for (int c = 0; c < GNC; ++c) {
        // ---- prefetch chunk c+1 into registers ----
        float4 pa[4], pb[4];
        if (c + 1 < GNC) {
            const int k0 = (c + 1) * GBK;
#pragma unroll
            for (int t = 0; t < 4; ++t) {
                int row = lrow + t * 32;
                int mg  = bm + row;
                pa[t] = make_float4(0.f, 0.f, 0.f, 0.f);
                if (mg < M) pa[t] = *(const float4*)(A + (size_t)mg * GK + k0 + lc4 * 4);
            }
#pragma unroll
            for (int t = 0; t < 4; ++t) {
                int row = lrow + t * 32;
                pb[t] = *(const float4*)(W + (size_t)(bn + row) * GK + k0 + lc4 * 4);
            }
        }

        // ---- compute chunk c ----
        {
            const uint32_t* sA = sm + (c & 1) * BUFW;
            const uint32_t* sB = sA + TILEW;
#pragma unroll
            for (int ks = 0; ks < 4; ++ks) {
                const int k = ks * 8;
                uint32_t af[2][4];
#pragma unroll
                for (int mf = 0; mf < 2; ++mf) {
                    const int m = wm + mf * 16 + grp;
                    af[mf][0] = sA[m * PADW + k + tig];
                    af[mf][1] = sA[(m + 8) * PADW + k + tig];
                    af[mf][2] = sA[m * PADW + k + tig + 4];
                    af[mf][3] = sA[(m + 8) * PADW + k + tig + 4];
                }
                uint32_t bf[8][2];
#pragma unroll
                for (int nf = 0; nf < 8; ++nf) {
                    const int n = wn + nf * 8 + grp;
                    bf[nf][0] = sB[n * PADW + k + tig];
                    bf[nf][1] = sB[n * PADW + k + tig + 4];
                }
#pragma unroll
                for (int mf = 0; mf < 2; ++mf)
#pragma unroll
                    for (int nf = 0; nf < 8; ++nf)
                        mma_m16n8k8_tf32(acc[mf][nf], af[mf], bf[nf]);
            }
        }

        // ---- store prefetched chunk to other buffer ----
        if (c + 1 < GNC) {
            uint32_t* sA = sm + ((c + 1) & 1) * BUFW;
            uint32_t* sB = sA + TILEW;
#pragma unroll
            for (int t = 0; t < 4; ++t) {
                int row = lrow + t * 32;
                uint32_t* d = &sA[row * PADW + lc4 * 4];
                ((uint4*)d)[0] = make_uint4(f2tf32(pa[t].x), f2tf32(pa[t].y),
                                            f2tf32(pa[t].z), f2tf32(pa[t].w));
            }
#pragma unroll
            for (int t = 0; t < 4; ++t) {
                int row = lrow + t * 32;
                uint32_t* d = &sB[row * PADW + lc4 * 4];
                ((uint4*)d)[0] = make_uint4(f2tf32(pb[t].x), f2tf32(pb[t].y),
                                            f2tf32(pb[t].z), f2tf32(pb[t].w));
            }
            __syncthreads();
        }
    }

    // ---- epilogue: write C with bias ----
#pragma unroll
    for (int mf = 0; mf < 2; ++mf) {
        const int mlo = bm + wm + mf * 16 + grp;
#pragma unroll
        for (int nf = 0; nf < 8; ++nf) {
            const int col = bn + wn + nf * 8 + 2 * tig;
            const float bx = __ldg(&bias[col]);
            const float by = __ldg(&bias[col + 1]);
            if (mlo < M) {
                float2 v = make_float2(acc[mf][nf][0] + bx, acc[mf][nf][1] + by);
                *(float2*)(C + (size_t)mlo * DM + col) = v;
            }
            if (mlo + 8 < M) {
                float2 v = make_float2(acc[mf][nf][2] + bx, acc[mf][nf][3] + by);
                *(float2*)(C + (size_t)(mlo + 8) * DM + col) = v;
            }
        }
    }
}

// ---------------------------------------------------------------------------
// Generic fp32 SIMT GEMM (small projections): C = A @ W^T + bias
// ---------------------------------------------------------------------------
#define BM 128
#define BN 64
#define BK 16
#define TM 8
#define TN 4

__global__ __launch_bounds__(256) void gemm_nt_bias(
    const float* __restrict__ A, const float* __restrict__ W,
    const float* __restrict__ bias, float* __restrict__ C,
    int M, int N, int K)
{
    __shared__ float As[BK][BM + 4];
    __shared__ float Bs[BK][BN];

    const int tx = threadIdx.x & 15;
    const int ty = threadIdx.x >> 4;
    const int bm = blockIdx.y * BM;
    const int bn = blockIdx.x * BN;

    float acc[TM][TN];
#pragma unroll
    for (int i = 0; i < TM; i++)
#pragma unroll
        for (int j = 0; j < TN; j++) acc[i][j] = 0.f;

    for (int k0 = 0; k0 < K; k0 += BK) {
#pragma unroll
        for (int t = 0; t < (BM * BK) / 256; ++t) {
            int i = threadIdx.x + t * 256;
            int m = i / BK, k = i % BK;
            float v = 0.f;
            if (bm + m < M) v = A[(size_t)(bm + m) * K + k0 + k];
            As[k][m] = v;
        }
#pragma unroll
        for (int t = 0; t < (BN * BK) / 256; ++t) {
            int i = threadIdx.x + t * 256;
            int n = i / BK, k = i % BK;
            float v = 0.f;
            if (bn + n < N) v = W[(size_t)(bn + n) * K + k0 + k];
            Bs[k][n] = v;
        }
        __syncthreads();

#pragma unroll
        for (int k = 0; k < BK; ++k) {
            float a[TM], b[TN];
#pragma unroll
            for (int i = 0; i < TM; i++) a[i] = As[k][ty * TM + i];
#pragma unroll
            for (int j = 0; j < TN; j++) b[j] = Bs[k][tx * TN + j];
#pragma unroll
            for (int i = 0; i < TM; i++)
#pragma unroll
                for (int j = 0; j < TN; j++) acc[i][j] += a[i] * b[j];
        }
        __syncthreads();
    }

#pragma unroll
    for (int i = 0; i < TM; i++) {
        int m = bm + ty * TM + i;
        if (m >= M) continue;
#pragma unroll
        for (int j = 0; j < TN; j++) {
            int n = bn + tx * TN + j;
            if (n < N) C[(size_t)m * N + n] = acc[i][j] + bias[n];
        }
    }
}

// ---------------------------------------------------------------------------
// Sampling kernel: one warp per (b, q, head); lane = head_dim channel.
// ---------------------------------------------------------------------------
__global__ __launch_bounds__(256) void msda_sample(
    const float* __restrict__ value,
    const float* __restrict__ offs,
    const float* __restrict__ attnl,
    const float* __restrict__ refp,
    float* __restrict__ out)
{
    const int bq   = blockIdx.x;
    const int b    = bq / Q_;
    const int head = threadIdx.x >> 5;
    const int lane = threadIdx.x & 31;

    const float rx = refp[bq * 4 + 0];
    const float ry = refp[bq * 4 + 1];
    const float rw = refp[bq * 4 + 2];
    const float rh = refp[bq * 4 + 3];

    const float* o  = offs  + (size_t)bq * 192 + head * (LP_ * 2);
    const float* al = attnl + (size_t)bq * 96  + head * LP_;

    float w[LP_];
    float mx = -1e30f;
#pragma unroll
    for (int p = 0; p < LP_; p++) { w[p] = al[p]; mx = fmaxf(mx, w[p]); }
    float sum = 0.f;
#pragma unroll
    for (int p = 0; p < LP_; p++) { w[p] = __expf(w[p] - mx); sum += w[p]; }
    const float inv = 1.f / sum;

    float acc = 0.f;
#pragma unroll
    for (int p = 0; p < LP_; p++) {
        const int lvl   = p >> 2;
        const int Wl    = (lvl == 0) ? 80 : (lvl == 1) ? 40 : 20;
        const int Hl    = Wl;
        const int start = (lvl == 0) ? 0 : (lvl == 1) ? 6400 : 8000;

        const float lx = rx + o[2 * p + 0] * 0.125f * rw;
        const float ly = ry + o[2 * p + 1] * 0.125f * rh;
        const float gx = lx * (float)Wl - 0.5f;
        const float gy = ly * (float)Hl - 0.5f;

        const float x0f = floorf(gx), y0f = floorf(gy);
        const int x0 = (int)x0f, y0 = (int)y0f;
        const int x1 = x0 + 1,  y1 = y0 + 1;
        const float wx1 = gx - x0f, wx0 = 1.f - wx1;
        const float wy1 = gy - y0f, wy0 = 1.f - wy1;

        const float aw = w[p] * inv;

        const size_t base = ((size_t)b * S_ + start) * DM + head * HD + lane;

        float v00 = 0.f, v10 = 0.f, v01 = 0.f, v11 = 0.f;
        const bool xv0 = (x0 >= 0) & (x0 < Wl);
        const bool xv1 = (x1 >= 0) & (x1 < Wl);
        const bool yv0 = (y0 >= 0) & (y0 < Hl);
        const bool yv1 = (y1 >= 0) & (y1 < Hl);
        if (yv0) {
            const size_t rb = base + (size_t)(y0 * Wl) * DM;
            if (xv0) v00 = value[rb + (size_t)x0 * DM];
            if (xv1) v10 = value[rb + (size_t)x1 * DM];
        }
        if (yv1) {
            const size_t rb = base + (size_t)(y1 * Wl) * DM;
            if (xv0) v01 = value[rb + (size_t)x0 * DM];
            if (xv1) v11 = value[rb + (size_t)x1 * DM];
        }
        acc += aw * (wx0 * wy0 * v00 + wx1 * wy0 * v10 +
                     wx0 * wy1 * v01 + wx1 * wy1 * v11);
    }

    out[(size_t)bq * DM + head * HD + lane] = acc;
}

// ---------------------------------------------------------------------------
extern "C" void kernel_launch(void* const* d_in, const int* in_sizes, int n_in,
                              void* d_out, int out_size)
{
    const float* hs      = (const float*)d_in[0];
    const float* ehs     = (const float*)d_in[1];
    const float* refp    = (const float*)d_in[2];
    const float* w_value = (const float*)d_in[3];
    const float* b_value = (const float*)d_in[4];
    const float* w_off   = (const float*)d_in[5];
    const float* b_off   = (const float*)d_in[6];
    const float* w_attn  = (const float*)d_in[7];
    const float* b_attn  = (const float*)d_in[8];
    const float* w_out   = (const float*)d_in[9];
    const float* b_out   = (const float*)d_in[10];
    float* out = (float*)d_out;

    float *pval, *poff, *pattn, *pmsda;
    cudaGetSymbolAddress((void**)&pval,  g_value);
    cudaGetSymbolAddress((void**)&poff,  g_offs);
    cudaGetSymbolAddress((void**)&pattn, g_attn);
    cudaGetSymbolAddress((void**)&pmsda, g_msda);

    const int dyn_smem = 2 * BUFW * 4;   // 73728 bytes
    cudaFuncSetAttribute(gemm_tf32_nt,
                         cudaFuncAttributeMaxDynamicSharedMemorySize, dyn_smem);

    // 1. value = ehs @ w_value^T + b_value   (tf32 tensor cores)
    gemm_tf32_nt<<<dim3(2, MVAL / 128), 256, dyn_smem>>>(ehs, w_value, b_value,
                                                         pval, MVAL);
    // 2. offsets = hs @ w_offsets^T + b
    gemm_nt_bias<<<dim3(3, (BQ + BM - 1) / BM), 256>>>(hs, w_off, b_off, poff,
                                                       BQ, 192, DM);
    // 3. attn logits = hs @ w_attn^T + b
    gemm_nt_bias<<<dim3(2, (BQ + BM - 1) / BM), 256>>>(hs, w_attn, b_attn, pattn,
                                                       BQ, 96, DM);
    // 4. softmax + bilinear sampling + weighted sum
    msda_sample<<<BQ, 256>>>(pval, poff, pattn, refp, pmsda);
    // 5. out = msda @ w_out^T + b_out   (tf32 tensor cores, M=4800)
    gemm_tf32_nt<<<dim3(2, (BQ + 127) / 128), 256, dyn_smem>>>(pmsda, w_out,
                                                               b_out, out, BQ);
}